// round 8
// baseline (speedup 1.0000x reference)
#include <cuda_runtime.h>
#include <cuda_fp16.h>
#include <cstdint>

#define OBS 128
#define NAGENT 16
#define HID 128
#define GE 256
#define LE 256
#define F1 512
#define F2 512
#define NACT 8
#define MAXB 2048
#define MAXM (MAXB * NAGENT)

// fp16 weight pack offsets (halves)
#define OFF_WCAT  0            // [128, 384] = [W_pre | W_loc]
#define OFF_WGCN  49152        // [2,128,128]
#define OFF_WPOST 81920        // [128,256]
#define OFF_W1    114688       // [512,512]
#define OFF_W2    376832       // [512,512]
#define WH_TOTAL  638976

__device__ __align__(16) __half g_wh[WH_TOTAL];
__device__ __align__(16) float  g_bcat[384];
__device__ __align__(16) __half g_xloc[MAXM * 384];   // [x | loc]
__device__ __align__(16) __half g_xbar[MAXB * HID];
__device__ __align__(16) __half g_s0[MAXB * HID];
__device__ __align__(16) __half g_s1[MAXB * HID];
__device__ __align__(16) __half g_gv[MAXB * GE];
__device__ __align__(16) float  g_G1[MAXB * F1];

#define BM 128
#define BN 128
#define BK 64

// hgemm dynamic smem (halves): stage st: A at st*17920 (128 x 72),
// B at st*17920+9216 (64 x 136). Epilogue overlay zs 128 x 136.
#define A_ST   17920
#define A_RS   72
#define B_OFF  9216
#define B_RS   136
#define SMEMB  71680

// mlp2 smem layout (halves)
#define Z1_RS    520
#define PA_OFF   66560                        // z1s = 128*520 halves
#define PA_ST    9216                         // A stage stride (128 x 72) -- FIX
#define PB_OFF   (PA_OFF + 2 * PA_ST)         // 84992
#define PB_ST    (64 * 136)                   // 8704
#define W3S_OFF  (PB_OFF + 2 * PB_ST)         // 102400
#define QACC_OFF (W3S_OFF + 8192)             // W3s = 4096 floats
#define MLP2_SMEM ((QACC_OFF + 2048) * 2)     // 225280 bytes

__device__ __forceinline__ void cp16(uint32_t dst, const void* src) {
    asm volatile("cp.async.cg.shared.global [%0], [%1], 16;\n" ::"r"(dst), "l"(src));
}
__device__ __forceinline__ uint32_t smem_u32(const void* p) {
    return (uint32_t)__cvta_generic_to_shared(p);
}

#define LDSM_A(dst, addr) \
    asm volatile("ldmatrix.sync.aligned.m8n8.x4.shared.b16 {%0,%1,%2,%3}, [%4];" \
                 : "=r"((dst)[0]), "=r"((dst)[1]), "=r"((dst)[2]), "=r"((dst)[3]) \
                 : "r"(addr))
#define LDSM_BT(dst, addr) \
    asm volatile("ldmatrix.sync.aligned.m8n8.x4.trans.shared.b16 {%0,%1,%2,%3}, [%4];" \
                 : "=r"((dst)[0]), "=r"((dst)[1]), "=r"((dst)[2]), "=r"((dst)[3]) \
                 : "r"(addr))
#define MMA16816(cc, a, b0v, b1v) \
    asm volatile("mma.sync.aligned.m16n8k16.row.col.f32.f16.f16.f32 " \
                 "{%0,%1,%2,%3}, {%4,%5,%6,%7}, {%8,%9}, {%0,%1,%2,%3};" \
                 : "+f"((cc)[0]), "+f"((cc)[1]), "+f"((cc)[2]), "+f"((cc)[3]) \
                 : "r"((a)[0]), "r"((a)[1]), "r"((a)[2]), "r"((a)[3]), \
                   "r"(b0v), "r"(b1v))

// ---------------------------------------------------------------------------
// fp16 HMMA GEMM. AF32: A fp32 converted inline. FUSE: 0 none,
// 1 = block x==0 also produces xbar (mean over 16-row groups of cols 0..127).
// BM=BN=128, BK=64, 256 threads, 8 warps @ 64x32.
// ---------------------------------------------------------------------------
template <int AF32, int FUSE>
__global__ __launch_bounds__(256) void hgemm(
    const void* __restrict__ Ap, const __half* __restrict__ B,
    __half* __restrict__ Ch, float* __restrict__ Cf,
    int M, int N, int K, int lda,
    const float* __restrict__ bias, const float* __restrict__ rowAdd,
    int doRelu, __half* __restrict__ aux_h)
{
    extern __shared__ __half S[];

    const int tid  = threadIdx.x;
    const int lane = tid & 31;
    const int wid  = tid >> 5;
    const int wm   = wid >> 2;
    const int wn   = wid & 3;
    const int brow = blockIdx.y * BM;
    const int bcol = blockIdx.x * BN;

    const __half* Ah = (const __half*)Ap;
    const float*  Af = (const float*)Ap;

    float c[4][4][4];
#pragma unroll
    for (int i = 0; i < 4; i++)
#pragma unroll
        for (int j = 0; j < 4; j++)
#pragma unroll
            for (int e = 0; e < 4; e++) c[i][j][e] = 0.f;

    const int nT = K / BK;

    auto loadStage = [&](int t, int st) {
        const int k0 = t * BK;
        __half* As = S + st * A_ST;
        __half* Bs = S + st * A_ST + B_OFF;
#pragma unroll
        for (int j = 0; j < 4; j++) {
            const int ch = j * 256 + tid;
            const int r = ch >> 3, cc = (ch & 7) * 8;
            if (AF32) {
                const float4* s =
                    (const float4*)(Af + (size_t)(brow + r) * lda + k0 + cc);
                float4 v0 = s[0], v1 = s[1];
                __half2 h0 = __floats2half2_rn(v0.x, v0.y);
                __half2 h1 = __floats2half2_rn(v0.z, v0.w);
                __half2 h2 = __floats2half2_rn(v1.x, v1.y);
                __half2 h3 = __floats2half2_rn(v1.z, v1.w);
                uint4 u;
                u.x = *(uint32_t*)&h0; u.y = *(uint32_t*)&h1;
                u.z = *(uint32_t*)&h2; u.w = *(uint32_t*)&h3;
                *(uint4*)&As[r * A_RS + cc] = u;
            } else {
                cp16(smem_u32(&As[r * A_RS + cc]),
                     Ah + (size_t)(brow + r) * lda + k0 + cc);
            }
        }
#pragma unroll
        for (int j = 0; j < 4; j++) {
            const int ch = j * 256 + tid;
            const int r = ch >> 4, cc = (ch & 15) * 8;
            cp16(smem_u32(&Bs[r * B_RS + cc]),
                 B + (size_t)(k0 + r) * N + bcol + cc);
        }
    };

    loadStage(0, 0);
    asm volatile("cp.async.commit_group;\n");

    for (int t = 0; t < nT; t++) {
        if (t + 1 < nT) loadStage(t + 1, (t + 1) & 1);
        asm volatile("cp.async.commit_group;\n");
        asm volatile("cp.async.wait_group 1;\n");
        __syncthreads();

        const __half* As = S + (t & 1) * A_ST;
        const __half* Bs = S + (t & 1) * A_ST + B_OFF;
#pragma unroll
        for (int ks = 0; ks < 4; ks++) {
            uint32_t a[4][4], b[2][4];
#pragma unroll
            for (int mi = 0; mi < 4; mi++)
                LDSM_A(a[mi], smem_u32(&As[(wm * 64 + mi * 16 + (lane & 15)) * A_RS +
                                           ks * 16 + (lane >> 4) * 8]));
#pragma unroll
            for (int pi = 0; pi < 2; pi++)
                LDSM_BT(b[pi], smem_u32(&Bs[(ks * 16 + (lane & 7) +
                                             ((lane >> 3) & 1) * 8) * B_RS +
                                            wn * 32 + pi * 16 + (lane >> 4) * 8]));
#pragma unroll
            for (int mi = 0; mi < 4; mi++)
#pragma unroll
                for (int ni = 0; ni < 4; ni++)
                    MMA16816(c[mi][ni], a[mi],
                             b[ni >> 1][(ni & 1) * 2], b[ni >> 1][(ni & 1) * 2 + 1]);
        }
        __syncthreads();
    }

    const bool stage = (FUSE == 1 && blockIdx.x == 0);
    __half* zs = S;

#pragma unroll
    for (int mi = 0; mi < 4; mi++) {
        const int rl0 = wm * 64 + mi * 16 + (lane >> 2);
        const int row  = brow + rl0;
        const int row2 = row + 8;
        const float* ra = rowAdd ? rowAdd + (size_t)(row >> 4) * N : nullptr;
#pragma unroll
        for (int ni = 0; ni < 4; ni++) {
            const int cl  = wn * 32 + ni * 8 + (lane & 3) * 2;
            const int col = bcol + cl;
            float v0 = c[mi][ni][0], v1 = c[mi][ni][1];
            float v2 = c[mi][ni][2], v3 = c[mi][ni][3];
            if (bias) {
                const float bb0 = bias[col], bb1 = bias[col + 1];
                v0 += bb0; v1 += bb1; v2 += bb0; v3 += bb1;
            }
            if (ra) {
                const float r0 = ra[col], r1 = ra[col + 1];
                v0 += r0; v1 += r1; v2 += r0; v3 += r1;
            }
            if (doRelu) {
                v0 = fmaxf(v0, 0.f); v1 = fmaxf(v1, 0.f);
                v2 = fmaxf(v2, 0.f); v3 = fmaxf(v3, 0.f);
            }
            __half2 h01 = __floats2half2_rn(v0, v1);
            __half2 h23 = __floats2half2_rn(v2, v3);
            if (Ch) {
                *(__half2*)&Ch[(size_t)row  * N + col] = h01;
                *(__half2*)&Ch[(size_t)row2 * N + col] = h23;
            } else {
                *(float2*)&Cf[(size_t)row  * N + col] = make_float2(v0, v1);
                *(float2*)&Cf[(size_t)row2 * N + col] = make_float2(v2, v3);
            }
            if (stage) {
                *(__half2*)&zs[rl0 * B_RS + cl]       = h01;
                *(__half2*)&zs[(rl0 + 8) * B_RS + cl] = h23;
            }
        }
    }

    if (FUSE == 1 && blockIdx.x == 0) {
        __syncthreads();
        const int s0 = brow >> 4;
#pragma unroll
        for (int j = 0; j < 4; j++) {
            const int idx = j * 256 + tid;
            const int s = idx >> 7, cc = idx & 127;
            float acc = 0.f;
#pragma unroll
            for (int r = 0; r < 16; r++)
                acc += __half2float(zs[(s * 16 + r) * B_RS + cc]);
            aux_h[(size_t)(s0 + s) * 128 + cc] = __float2half_rn(acc * (1.f / 16.f));
        }
    }
}

// ---------------------------------------------------------------------------
// Megakernel: per 128-row block,
//   z1s = relu(loc @ W1bot + G1[sample])  (kept in smem, [128,512])
//   for each 128-col block of z2: t = relu(z1s @ W2blk + b2blk); qacc += t @ W3blk
//   q = qacc + b3
// ---------------------------------------------------------------------------
__global__ __launch_bounds__(256) void mlp2(
    const __half* __restrict__ loc,          // xloc+128, lda=384
    const __half* __restrict__ W1b,          // [256,512] (rows 256.. of W1)
    const float* __restrict__ G1,            // [B,512]
    const float* __restrict__ b2,
    const __half* __restrict__ W2,           // [512,512]
    const float* __restrict__ W3,            // [512,8]
    const float* __restrict__ b3,
    float* __restrict__ q)                   // [M,8]
{
    extern __shared__ __half S[];
    __half* z1s = S;
    float*  W3s  = (float*)(S + W3S_OFF);
    float*  qacc = (float*)(S + QACC_OFF);

    const int tid  = threadIdx.x;
    const int lane = tid & 31;
    const int wid  = tid >> 5;
    const int wm   = wid >> 2;
    const int wn   = wid & 3;
    const int brow = blockIdx.x * 128;

#pragma unroll
    for (int j = 0; j < 4; j++)
        ((float4*)W3s)[j * 256 + tid] = ((const float4*)W3)[j * 256 + tid];
    ((float4*)qacc)[tid] = make_float4(0.f, 0.f, 0.f, 0.f);

    // ---------------- phase 1: z1 tile into smem ----------------
    auto loadA1 = [&](int t, int st) {
        __half* As = S + PA_OFF + st * PA_ST;
        const int k0 = t * 64;
#pragma unroll
        for (int j = 0; j < 4; j++) {
            const int ch = j * 256 + tid;
            const int r = ch >> 3, cc = (ch & 7) * 8;
            cp16(smem_u32(&As[r * A_RS + cc]),
                 loc + (size_t)(brow + r) * 384 + k0 + cc);
        }
    };
    auto loadB = [&](const __half* Bp, int t, int st) {
        __half* Bs = S + PB_OFF + st * PB_ST;
        const int k0 = t * 64;
#pragma unroll
        for (int j = 0; j < 4; j++) {
            const int ch = j * 256 + tid;
            const int r = ch >> 4, cc = (ch & 15) * 8;
            cp16(smem_u32(&Bs[r * B_RS + cc]),
                 Bp + (size_t)(k0 + r) * 512 + cc);
        }
    };

#pragma unroll 1
    for (int nb = 0; nb < 4; nb++) {
        __syncthreads();
        const __half* Bp = W1b + nb * 128;
        float c[4][4][4];
#pragma unroll
        for (int i = 0; i < 4; i++)
#pragma unroll
            for (int j = 0; j < 4; j++)
#pragma unroll
                for (int e = 0; e < 4; e++) c[i][j][e] = 0.f;

        loadA1(0, 0); loadB(Bp, 0, 0);
        asm volatile("cp.async.commit_group;\n");
#pragma unroll 1
        for (int t = 0; t < 4; t++) {
            if (t + 1 < 4) { loadA1(t + 1, (t + 1) & 1); loadB(Bp, t + 1, (t + 1) & 1); }
            asm volatile("cp.async.commit_group;\n");
            asm volatile("cp.async.wait_group 1;\n");
            __syncthreads();
            const __half* As = S + PA_OFF + (t & 1) * PA_ST;
            const __half* Bs = S + PB_OFF + (t & 1) * PB_ST;
#pragma unroll
            for (int ks = 0; ks < 4; ks++) {
                uint32_t a[4][4], b[2][4];
#pragma unroll
                for (int mi = 0; mi < 4; mi++)
                    LDSM_A(a[mi], smem_u32(&As[(wm * 64 + mi * 16 + (lane & 15)) * A_RS +
                                               ks * 16 + (lane >> 4) * 8]));
#pragma unroll
                for (int pi = 0; pi < 2; pi++)
                    LDSM_BT(b[pi], smem_u32(&Bs[(ks * 16 + (lane & 7) +
                                                 ((lane >> 3) & 1) * 8) * B_RS +
                                                wn * 32 + pi * 16 + (lane >> 4) * 8]));
#pragma unroll
                for (int mi = 0; mi < 4; mi++)
#pragma unroll
                    for (int ni = 0; ni < 4; ni++)
                        MMA16816(c[mi][ni], a[mi],
                                 b[ni >> 1][(ni & 1) * 2], b[ni >> 1][(ni & 1) * 2 + 1]);
            }
            __syncthreads();
        }
        // epilogue -> z1s
#pragma unroll
        for (int mi = 0; mi < 4; mi++) {
            const int rl0 = wm * 64 + mi * 16 + (lane >> 2);
            const float* ra = G1 + (size_t)((brow + rl0) >> 4) * 512 + nb * 128;
#pragma unroll
            for (int ni = 0; ni < 4; ni++) {
                const int cl = wn * 32 + ni * 8 + (lane & 3) * 2;
                float v0 = c[mi][ni][0] + ra[cl];
                float v1 = c[mi][ni][1] + ra[cl + 1];
                float v2 = c[mi][ni][2] + ra[cl];
                float v3 = c[mi][ni][3] + ra[cl + 1];
                v0 = fmaxf(v0, 0.f); v1 = fmaxf(v1, 0.f);
                v2 = fmaxf(v2, 0.f); v3 = fmaxf(v3, 0.f);
                *(__half2*)&z1s[rl0 * Z1_RS + nb * 128 + cl] = __floats2half2_rn(v0, v1);
                *(__half2*)&z1s[(rl0 + 8) * Z1_RS + nb * 128 + cl] = __floats2half2_rn(v2, v3);
            }
        }
    }

    // ---------------- phase 2: z2 blocks + q accumulation ----------------
#pragma unroll 1
    for (int nb2 = 0; nb2 < 4; nb2++) {
        __syncthreads();   // z1s ready / previous z2 stage consumed
        const __half* Bp = W2 + nb2 * 128;
        float c[4][4][4];
#pragma unroll
        for (int i = 0; i < 4; i++)
#pragma unroll
            for (int j = 0; j < 4; j++)
#pragma unroll
                for (int e = 0; e < 4; e++) c[i][j][e] = 0.f;

        loadB(Bp, 0, 0);
        asm volatile("cp.async.commit_group;\n");
#pragma unroll 1
        for (int t = 0; t < 8; t++) {
            if (t + 1 < 8) loadB(Bp, t + 1, (t + 1) & 1);
            asm volatile("cp.async.commit_group;\n");
            asm volatile("cp.async.wait_group 1;\n");
            __syncthreads();
            const __half* Bs = S + PB_OFF + (t & 1) * PB_ST;
#pragma unroll
            for (int ks = 0; ks < 4; ks++) {
                uint32_t a[4][4], b[2][4];
#pragma unroll
                for (int mi = 0; mi < 4; mi++)
                    LDSM_A(a[mi], smem_u32(&z1s[(wm * 64 + mi * 16 + (lane & 15)) * Z1_RS +
                                                t * 64 + ks * 16 + (lane >> 4) * 8]));
#pragma unroll
                for (int pi = 0; pi < 2; pi++)
                    LDSM_BT(b[pi], smem_u32(&Bs[(ks * 16 + (lane & 7) +
                                                 ((lane >> 3) & 1) * 8) * B_RS +
                                                wn * 32 + pi * 16 + (lane >> 4) * 8]));
#pragma unroll
                for (int mi = 0; mi < 4; mi++)
#pragma unroll
                    for (int ni = 0; ni < 4; ni++)
                        MMA16816(c[mi][ni], a[mi],
                                 b[ni >> 1][(ni & 1) * 2], b[ni >> 1][(ni & 1) * 2 + 1]);
            }
            __syncthreads();
        }
        // epilogue -> z2 stage (reuse pipeB region)
        __half* z2s = S + PB_OFF;
#pragma unroll
        for (int mi = 0; mi < 4; mi++) {
            const int rl0 = wm * 64 + mi * 16 + (lane >> 2);
#pragma unroll
            for (int ni = 0; ni < 4; ni++) {
                const int cl = wn * 32 + ni * 8 + (lane & 3) * 2;
                const float bb0 = b2[nb2 * 128 + cl], bb1 = b2[nb2 * 128 + cl + 1];
                float v0 = fmaxf(c[mi][ni][0] + bb0, 0.f);
                float v1 = fmaxf(c[mi][ni][1] + bb1, 0.f);
                float v2 = fmaxf(c[mi][ni][2] + bb0, 0.f);
                float v3 = fmaxf(c[mi][ni][3] + bb1, 0.f);
                *(__half2*)&z2s[rl0 * B_RS + cl]       = __floats2half2_rn(v0, v1);
                *(__half2*)&z2s[(rl0 + 8) * B_RS + cl] = __floats2half2_rn(v2, v3);
            }
        }
        __syncthreads();
        // q partial: warp per 16 rows
        const __half2* z2s2 = (const __half2*)z2s;
#pragma unroll 1
        for (int rr = 0; rr < 16; rr++) {
            const int rl = wid * 16 + rr;
            float acc[NACT] = {};
#pragma unroll
            for (int it = 0; it < 2; it++) {
                const int k2 = it * 32 + lane;
                float2 z = __half22float2(z2s2[rl * (B_RS / 2) + k2]);
                const float* w0 = &W3s[(nb2 * 128 + 2 * k2) * NACT];
#pragma unroll
                for (int n = 0; n < NACT; n++)
                    acc[n] = fmaf(z.x, w0[n], fmaf(z.y, w0[NACT + n], acc[n]));
            }
#pragma unroll
            for (int n = 0; n < NACT; n++)
#pragma unroll
                for (int off = 16; off > 0; off >>= 1)
                    acc[n] += __shfl_xor_sync(0xffffffff, acc[n], off);
            if (lane == 0) {
#pragma unroll
                for (int n = 0; n < NACT; n++) qacc[rl * NACT + n] += acc[n];
            }
        }
    }

    __syncthreads();
    {
        float4 bb = ((const float4*)b3)[tid & 1];
        float4 v = ((float4*)qacc)[tid];
        v.x += bb.x; v.y += bb.y; v.z += bb.z; v.w += bb.w;
        ((float4*)(q + (size_t)brow * NACT))[tid] = v;
    }
}

// ---------------------------------------------------------------------------
__global__ void convW(const float* __restrict__ Wpre, const float* __restrict__ Wloc,
                      const float* __restrict__ Wgcn, const float* __restrict__ Wpost,
                      const float* __restrict__ W1, const float* __restrict__ W2,
                      __half* __restrict__ out)
{
    int idx = blockIdx.x * blockDim.x + threadIdx.x;
    if (idx >= WH_TOTAL) return;
    float v;
    if (idx < OFF_WGCN) {
        int k = idx / 384, j = idx % 384;
        v = (j < 128) ? Wpre[k * 128 + j] : Wloc[k * 256 + (j - 128)];
    }
    else if (idx < OFF_WPOST) v = Wgcn[idx - OFF_WGCN];
    else if (idx < OFF_W1)    v = Wpost[idx - OFF_WPOST];
    else if (idx < OFF_W2)    v = W1[idx - OFF_W1];
    else                      v = W2[idx - OFF_W2];
    out[idx] = __float2half_rn(v);
}

__global__ void fillBcat(const float* __restrict__ b_pre,
                         const float* __restrict__ b_loc, float* __restrict__ bcat)
{
    int i = threadIdx.x;
    bcat[i] = (i < 128) ? b_pre[i] : b_loc[i - 128];
}

// ---------------------------------------------------------------------------
extern "C" void kernel_launch(void* const* d_in, const int* in_sizes, int n_in,
                              void* d_out, int out_size)
{
    const float* obs    = (const float*)d_in[0];
    const float* W_pre  = (const float*)d_in[1];
    const float* b_pre  = (const float*)d_in[2];
    const float* W_gcn  = (const float*)d_in[3];
    const float* b_gcn  = (const float*)d_in[4];
    const float* W_post = (const float*)d_in[5];
    const float* b_post = (const float*)d_in[6];
    const float* W_loc  = (const float*)d_in[7];
    const float* b_loc  = (const float*)d_in[8];
    const float* W1     = (const float*)d_in[9];
    const float* b1     = (const float*)d_in[10];
    const float* W2     = (const float*)d_in[11];
    const float* b2     = (const float*)d_in[12];
    const float* W3     = (const float*)d_in[13];
    const float* b3     = (const float*)d_in[14];
    float* q = (float*)d_out;

    const int Bsz = in_sizes[0] / (NAGENT * OBS);   // 2048
    const int M   = Bsz * NAGENT;                   // 32768

    __half *wh, *xloc, *xbar, *s0, *s1, *gv;
    float *bcat, *G1;
    cudaGetSymbolAddress((void**)&wh,   g_wh);
    cudaGetSymbolAddress((void**)&bcat, g_bcat);
    cudaGetSymbolAddress((void**)&xloc, g_xloc);
    cudaGetSymbolAddress((void**)&xbar, g_xbar);
    cudaGetSymbolAddress((void**)&s0,   g_s0);
    cudaGetSymbolAddress((void**)&s1,   g_s1);
    cudaGetSymbolAddress((void**)&gv,   g_gv);
    cudaGetSymbolAddress((void**)&G1,   g_G1);

    cudaFuncSetAttribute(hgemm<1, 1>, cudaFuncAttributeMaxDynamicSharedMemorySize, SMEMB);
    cudaFuncSetAttribute(hgemm<0, 0>, cudaFuncAttributeMaxDynamicSharedMemorySize, SMEMB);
    cudaFuncSetAttribute(mlp2, cudaFuncAttributeMaxDynamicSharedMemorySize, MLP2_SMEM);

    convW<<<(WH_TOTAL + 255) / 256, 256>>>(W_pre, W_loc, W_gcn, W_post, W1, W2, wh);
    fillBcat<<<1, 384>>>(b_pre, b_loc, bcat);

    // 1) [x|loc] = relu(obs @ [W_pre|W_loc] + bcat); block x==0 also emits xbar
    hgemm<1, 1><<<dim3(3, M / BM), 256, SMEMB>>>(obs, wh + OFF_WCAT, xloc, nullptr,
                                                 M, 384, OBS, OBS, bcat, nullptr, 1,
                                                 xbar);
    // 2) collapsed GCN chain (per-sample rows)
    hgemm<0, 0><<<dim3(1, Bsz / BM), 256, SMEMB>>>(xbar, wh + OFF_WGCN, s0, nullptr,
                                                   Bsz, HID, HID, HID, b_gcn, nullptr, 1,
                                                   nullptr);
    hgemm<0, 0><<<dim3(1, Bsz / BM), 256, SMEMB>>>(s0, wh + OFF_WGCN + HID * HID, s1,
                                                   nullptr, Bsz, HID, HID, HID,
                                                   b_gcn + HID, nullptr, 1, nullptr);
    hgemm<0, 0><<<dim3(GE / BN, Bsz / BM), 256, SMEMB>>>(s1, wh + OFF_WPOST, gv, nullptr,
                                                         Bsz, GE, HID, HID, b_post,
                                                         nullptr, 1, nullptr);
    // 3) G1 = g @ W1[:256,:] + b1 (fp32 out)
    hgemm<0, 0><<<dim3(F1 / BN, Bsz / BM), 256, SMEMB>>>(gv, wh + OFF_W1, nullptr, G1,
                                                         Bsz, F1, GE, GE, b1, nullptr, 0,
                                                         nullptr);
    // 4) megakernel: z1 (smem) -> z2 blocks -> q
    mlp2<<<M / 128, 256, MLP2_SMEM>>>(xloc + 128, wh + OFF_W1 + GE * F1, G1, b2,
                                      wh + OFF_W2, W3, b3, q);
}

// round 10
// speedup vs baseline: 1.4254x; 1.4254x over previous
#include <cuda_runtime.h>
#include <cuda_fp16.h>
#include <cstdint>

#define OBS 128
#define NAGENT 16
#define HID 128
#define GE 256
#define LE 256
#define F1 512
#define F2 512
#define NACT 8
#define MAXB 2048
#define MAXM (MAXB * NAGENT)

// fp16 weight pack offsets (halves)
#define OFF_WCAT  0            // [128, 384] = [W_pre | W_loc]
#define OFF_WGCN  49152        // [2,128,128]
#define OFF_WPOST 81920        // [128,256]
#define OFF_W1    114688       // [512,512]
#define OFF_W2    376832       // [512,512]
#define WH_TOTAL  638976

__device__ __align__(16) __half g_wh[WH_TOTAL];
__device__ __align__(16) float  g_bcat[384];
__device__ __align__(16) __half g_loc[MAXM * 256];    // compact loc
__device__ __align__(16) __half g_xbar[MAXB * HID];
__device__ __align__(16) float  g_G1[MAXB * F1];
__device__ __align__(16) __half g_z1[MAXM * F1];
__device__ __align__(16) float  g_qpart[4 * MAXM * NACT];

#define BM 128
#define BN 128
#define BK 64

// hgemm dynamic smem (halves): stage st: A at st*17920 (128 x 72),
// B at st*17920+9216 (64 x 136). Epilogue overlay zs 128 x 136 + W3s floats.
#define A_ST   17920
#define A_RS   72
#define B_OFF  9216
#define B_RS   136
#define PB_ST  8704
#define SMEMB  71680

// chain kernel smem (halves)
#define CH_ACTA 0
#define CH_ACTB 17408
#define CH_ACTY 34816          // 128 x 264
#define CH_BP   68608          // 2 x 8704
#define CH_SMEM ((CH_BP + 2 * PB_ST) * 2)    // 172032 bytes

__device__ __forceinline__ void cp16(uint32_t dst, const void* src) {
    asm volatile("cp.async.cg.shared.global [%0], [%1], 16;\n" ::"r"(dst), "l"(src));
}
__device__ __forceinline__ uint32_t smem_u32(const void* p) {
    return (uint32_t)__cvta_generic_to_shared(p);
}

#define LDSM_A(dst, addr) \
    asm volatile("ldmatrix.sync.aligned.m8n8.x4.shared.b16 {%0,%1,%2,%3}, [%4];" \
                 : "=r"((dst)[0]), "=r"((dst)[1]), "=r"((dst)[2]), "=r"((dst)[3]) \
                 : "r"(addr))
#define LDSM_BT(dst, addr) \
    asm volatile("ldmatrix.sync.aligned.m8n8.x4.trans.shared.b16 {%0,%1,%2,%3}, [%4];" \
                 : "=r"((dst)[0]), "=r"((dst)[1]), "=r"((dst)[2]), "=r"((dst)[3]) \
                 : "r"(addr))
#define MMA16816(cc, a, b0v, b1v) \
    asm volatile("mma.sync.aligned.m16n8k16.row.col.f32.f16.f16.f32 " \
                 "{%0,%1,%2,%3}, {%4,%5,%6,%7}, {%8,%9}, {%0,%1,%2,%3};" \
                 : "+f"((cc)[0]), "+f"((cc)[1]), "+f"((cc)[2]), "+f"((cc)[3]) \
                 : "r"((a)[0]), "r"((a)[1]), "r"((a)[2]), "r"((a)[3]), \
                   "r"(b0v), "r"(b1v))

// ---------------------------------------------------------------------------
// fp16 HMMA GEMM. AF32: A fp32 converted inline. FUSE:
//  0 = plain; 1 = skip writes for cols < ocol; block x==0 also emits xbar
//      (mean over 16-row groups of cols 0..127);
//  2 = no C write; q_part[bx] = relu-tile @ W3[bcol:bcol+128,:8] (aux_f=W3).
// BM=BN=128, BK=64, 256 threads, 8 warps @ 64x32.
// ---------------------------------------------------------------------------
template <int AF32, int FUSE>
__global__ __launch_bounds__(256) void hgemm(
    const void* __restrict__ Ap, const __half* __restrict__ B,
    __half* __restrict__ Ch, float* __restrict__ Cf,
    int M, int N, int K, int lda, int ldc, int ocol,
    const float* __restrict__ bias, const float* __restrict__ rowAdd,
    int doRelu, __half* __restrict__ aux_h, const float* __restrict__ aux_f)
{
    extern __shared__ __half S[];

    const int tid  = threadIdx.x;
    const int lane = tid & 31;
    const int wid  = tid >> 5;
    const int wm   = wid >> 2;
    const int wn   = wid & 3;
    const int brow = blockIdx.y * BM;
    const int bcol = blockIdx.x * BN;

    const __half* Ah = (const __half*)Ap;
    const float*  Af = (const float*)Ap;

    float c[4][4][4];
#pragma unroll
    for (int i = 0; i < 4; i++)
#pragma unroll
        for (int j = 0; j < 4; j++)
#pragma unroll
            for (int e = 0; e < 4; e++) c[i][j][e] = 0.f;

    const int nT = K / BK;

    auto loadStage = [&](int t, int st) {
        const int k0 = t * BK;
        __half* As = S + st * A_ST;
        __half* Bs = S + st * A_ST + B_OFF;
#pragma unroll
        for (int j = 0; j < 4; j++) {
            const int ch = j * 256 + tid;
            const int r = ch >> 3, cc = (ch & 7) * 8;
            if (AF32) {
                const float4* s =
                    (const float4*)(Af + (size_t)(brow + r) * lda + k0 + cc);
                float4 v0 = s[0], v1 = s[1];
                __half2 h0 = __floats2half2_rn(v0.x, v0.y);
                __half2 h1 = __floats2half2_rn(v0.z, v0.w);
                __half2 h2 = __floats2half2_rn(v1.x, v1.y);
                __half2 h3 = __floats2half2_rn(v1.z, v1.w);
                uint4 u;
                u.x = *(uint32_t*)&h0; u.y = *(uint32_t*)&h1;
                u.z = *(uint32_t*)&h2; u.w = *(uint32_t*)&h3;
                *(uint4*)&As[r * A_RS + cc] = u;
            } else {
                cp16(smem_u32(&As[r * A_RS + cc]),
                     Ah + (size_t)(brow + r) * lda + k0 + cc);
            }
        }
#pragma unroll
        for (int j = 0; j < 4; j++) {
            const int ch = j * 256 + tid;
            const int r = ch >> 4, cc = (ch & 15) * 8;
            cp16(smem_u32(&Bs[r * B_RS + cc]),
                 B + (size_t)(k0 + r) * N + bcol + cc);
        }
    };

    loadStage(0, 0);
    asm volatile("cp.async.commit_group;\n");

    for (int t = 0; t < nT; t++) {
        if (t + 1 < nT) loadStage(t + 1, (t + 1) & 1);
        asm volatile("cp.async.commit_group;\n");
        asm volatile("cp.async.wait_group 1;\n");
        __syncthreads();

        const __half* As = S + (t & 1) * A_ST;
        const __half* Bs = S + (t & 1) * A_ST + B_OFF;
#pragma unroll
        for (int ks = 0; ks < 4; ks++) {
            uint32_t a[4][4], b[2][4];
#pragma unroll
            for (int mi = 0; mi < 4; mi++)
                LDSM_A(a[mi], smem_u32(&As[(wm * 64 + mi * 16 + (lane & 15)) * A_RS +
                                           ks * 16 + (lane >> 4) * 8]));
#pragma unroll
            for (int pi = 0; pi < 2; pi++)
                LDSM_BT(b[pi], smem_u32(&Bs[(ks * 16 + (lane & 7) +
                                             ((lane >> 3) & 1) * 8) * B_RS +
                                            wn * 32 + pi * 16 + (lane >> 4) * 8]));
#pragma unroll
            for (int mi = 0; mi < 4; mi++)
#pragma unroll
                for (int ni = 0; ni < 4; ni++)
                    MMA16816(c[mi][ni], a[mi],
                             b[ni >> 1][(ni & 1) * 2], b[ni >> 1][(ni & 1) * 2 + 1]);
        }
        __syncthreads();
    }

    const bool stage = (FUSE == 2) || (FUSE == 1 && blockIdx.x == 0);
    __half* zs = S;

#pragma unroll
    for (int mi = 0; mi < 4; mi++) {
        const int rl0 = wm * 64 + mi * 16 + (lane >> 2);
        const int row  = brow + rl0;
        const int row2 = row + 8;
        const float* ra = rowAdd ? rowAdd + (size_t)(row >> 4) * N : nullptr;
#pragma unroll
        for (int ni = 0; ni < 4; ni++) {
            const int cl  = wn * 32 + ni * 8 + (lane & 3) * 2;
            const int col = bcol + cl;
            float v0 = c[mi][ni][0], v1 = c[mi][ni][1];
            float v2 = c[mi][ni][2], v3 = c[mi][ni][3];
            if (bias) {
                const float bb0 = bias[col], bb1 = bias[col + 1];
                v0 += bb0; v1 += bb1; v2 += bb0; v3 += bb1;
            }
            if (ra) {
                const float r0 = ra[col], r1 = ra[col + 1];
                v0 += r0; v1 += r1; v2 += r0; v3 += r1;
            }
            if (doRelu) {
                v0 = fmaxf(v0, 0.f); v1 = fmaxf(v1, 0.f);
                v2 = fmaxf(v2, 0.f); v3 = fmaxf(v3, 0.f);
            }
            __half2 h01 = __floats2half2_rn(v0, v1);
            __half2 h23 = __floats2half2_rn(v2, v3);
            if (FUSE != 2 && (ocol == 0 || col >= ocol)) {
                if (Ch) {
                    *(__half2*)&Ch[(size_t)row  * ldc + col - ocol] = h01;
                    *(__half2*)&Ch[(size_t)row2 * ldc + col - ocol] = h23;
                } else {
                    *(float2*)&Cf[(size_t)row  * ldc + col - ocol] = make_float2(v0, v1);
                    *(float2*)&Cf[(size_t)row2 * ldc + col - ocol] = make_float2(v2, v3);
                }
            }
            if (stage) {
                *(__half2*)&zs[rl0 * B_RS + cl]       = h01;
                *(__half2*)&zs[(rl0 + 8) * B_RS + cl] = h23;
            }
        }
    }

    if (FUSE == 1 && blockIdx.x == 0) {
        __syncthreads();
        const int s0 = brow >> 4;
#pragma unroll
        for (int j = 0; j < 4; j++) {
            const int idx = j * 256 + tid;
            const int s = idx >> 7, cc = idx & 127;
            float acc = 0.f;
#pragma unroll
            for (int r = 0; r < 16; r++)
                acc += __half2float(zs[(s * 16 + r) * B_RS + cc]);
            aux_h[(size_t)(s0 + s) * 128 + cc] = __float2half_rn(acc * (1.f / 16.f));
        }
    }

    if (FUSE == 2) {
        __syncthreads();
        float* W3s = (float*)(zs + 128 * B_RS);
        {
            const float4* src = (const float4*)(aux_f + (size_t)bcol * NACT);
            ((float4*)W3s)[tid] = src[tid];   // 256 float4 = 1024 floats
        }
        __syncthreads();
        const __half2* zs2 = (const __half2*)zs;
        float* qp = Cf + (size_t)blockIdx.x * M * NACT;
        for (int rr = 0; rr < 16; rr++) {
            const int rl = wid * 16 + rr;
            float acc[NACT] = {};
#pragma unroll
            for (int it = 0; it < 2; it++) {
                const int k2 = it * 32 + lane;
                float2 z = __half22float2(zs2[rl * (B_RS / 2) + k2]);
                const float* w0 = &W3s[(2 * k2) * NACT];
#pragma unroll
                for (int n = 0; n < NACT; n++)
                    acc[n] = fmaf(z.x, w0[n], fmaf(z.y, w0[NACT + n], acc[n]));
            }
#pragma unroll
            for (int n = 0; n < NACT; n++)
#pragma unroll
                for (int off = 16; off > 0; off >>= 1)
                    acc[n] += __shfl_xor_sync(0xffffffff, acc[n], off);
            if (lane == 0) {
                float* o = qp + (size_t)(brow + rl) * NACT;
#pragma unroll
                for (int n = 0; n < NACT; n++) o[n] = acc[n];
            }
        }
    }
}

// ---------------------------------------------------------------------------
// Pipelined 128xK @ Kx128 block into accumulators; A from smem act buffer.
// ---------------------------------------------------------------------------
__device__ __forceinline__ void chain_gemm(
    const __half* __restrict__ act, int actS,
    const __half* __restrict__ Wg, int ldw, int wcol, int K,
    __half* __restrict__ bp, float c[4][4][4],
    int tid, int lane, int wm, int wn)
{
#pragma unroll
    for (int i = 0; i < 4; i++)
#pragma unroll
        for (int j = 0; j < 4; j++)
#pragma unroll
            for (int e = 0; e < 4; e++) c[i][j][e] = 0.f;

    const int nT = K >> 6;
    auto loadB = [&](int t, int st) {
        const int k0 = t * 64;
        __half* Bs = bp + st * PB_ST;
#pragma unroll
        for (int j = 0; j < 4; j++) {
            const int ch = j * 256 + tid;
            const int r = ch >> 4, cc = (ch & 15) * 8;
            cp16(smem_u32(&Bs[r * B_RS + cc]),
                 Wg + (size_t)(k0 + r) * ldw + wcol + cc);
        }
    };

    loadB(0, 0);
    asm volatile("cp.async.commit_group;\n");
    for (int t = 0; t < nT; t++) {
        if (t + 1 < nT) loadB(t + 1, (t + 1) & 1);
        asm volatile("cp.async.commit_group;\n");
        asm volatile("cp.async.wait_group 1;\n");
        __syncthreads();
        const __half* Bs = bp + (t & 1) * PB_ST;
#pragma unroll
        for (int ks = 0; ks < 4; ks++) {
            uint32_t a[4][4], b[2][4];
#pragma unroll
            for (int mi = 0; mi < 4; mi++)
                LDSM_A(a[mi], smem_u32(&act[(wm * 64 + mi * 16 + (lane & 15)) * actS +
                                            t * 64 + ks * 16 + (lane >> 4) * 8]));
#pragma unroll
            for (int pi = 0; pi < 2; pi++)
                LDSM_BT(b[pi], smem_u32(&Bs[(ks * 16 + (lane & 7) +
                                             ((lane >> 3) & 1) * 8) * B_RS +
                                            wn * 32 + pi * 16 + (lane >> 4) * 8]));
#pragma unroll
            for (int mi = 0; mi < 4; mi++)
#pragma unroll
                for (int ni = 0; ni < 4; ni++)
                    MMA16816(c[mi][ni], a[mi],
                             b[ni >> 1][(ni & 1) * 2], b[ni >> 1][(ni & 1) * 2 + 1]);
        }
        __syncthreads();
    }
}

// NOTE: bias indexed by cl (which already includes wn*32) — pass PLAIN base.
__device__ __forceinline__ void chain_epi_smem(
    float c[4][4][4], __half* out, int outS, int ocol,
    const float* __restrict__ bias, int wm, int wn, int lane)
{
#pragma unroll
    for (int mi = 0; mi < 4; mi++) {
        const int rl0 = wm * 64 + mi * 16 + (lane >> 2);
#pragma unroll
        for (int ni = 0; ni < 4; ni++) {
            const int cl = wn * 32 + ni * 8 + (lane & 3) * 2;
            const float bb0 = bias[cl], bb1 = bias[cl + 1];
            float v0 = fmaxf(c[mi][ni][0] + bb0, 0.f);
            float v1 = fmaxf(c[mi][ni][1] + bb1, 0.f);
            float v2 = fmaxf(c[mi][ni][2] + bb0, 0.f);
            float v3 = fmaxf(c[mi][ni][3] + bb1, 0.f);
            *(__half2*)&out[rl0 * outS + ocol + cl]       = __floats2half2_rn(v0, v1);
            *(__half2*)&out[(rl0 + 8) * outS + ocol + cl] = __floats2half2_rn(v2, v3);
        }
    }
}

// ---------------------------------------------------------------------------
// Fused per-sample chain: xbar -> s0 -> s1 -> gv -> G1 (global, fp32).
// grid = Bsz/128, 256 threads.
// ---------------------------------------------------------------------------
__global__ __launch_bounds__(256) void chain(
    const __half* __restrict__ xbar, const __half* __restrict__ wh,
    const float* __restrict__ b_gcn, const float* __restrict__ b_post,
    const float* __restrict__ b1, float* __restrict__ G1)
{
    extern __shared__ __half S[];
    __half* actA = S + CH_ACTA;
    __half* actB = S + CH_ACTB;
    __half* actY = S + CH_ACTY;
    __half* bp   = S + CH_BP;

    const int tid = threadIdx.x, lane = tid & 31, wid = tid >> 5;
    const int wm = wid >> 2, wn = wid & 3;
    const int srow = blockIdx.x * 128;

    // load xbar tile [128,128] -> actA (stride 136)
#pragma unroll
    for (int j = 0; j < 8; j++) {
        const int ch = j * 256 + tid;
        const int r = ch >> 4, cc = (ch & 15) * 8;
        cp16(smem_u32(&actA[r * 136 + cc]), xbar + (size_t)(srow + r) * 128 + cc);
    }
    asm volatile("cp.async.commit_group;\ncp.async.wait_group 0;\n");
    __syncthreads();

    float c[4][4][4];

    // s0 = relu(xbar @ Wgcn0 + b_gcn0) -> actB
    chain_gemm(actA, 136, wh + OFF_WGCN, 128, 0, 128, bp, c, tid, lane, wm, wn);
    chain_epi_smem(c, actB, 136, 0, b_gcn, wm, wn, lane);
    __syncthreads();

    // s1 = relu(s0 @ Wgcn1 + b_gcn1) -> actA
    chain_gemm(actB, 136, wh + OFF_WGCN + 16384, 128, 0, 128, bp, c, tid, lane, wm, wn);
    chain_epi_smem(c, actA, 136, 0, b_gcn + 128, wm, wn, lane);
    __syncthreads();

    // gv = relu(s1 @ Wpost + b_post) -> actY [128,256]
#pragma unroll 1
    for (int nb = 0; nb < 2; nb++) {
        chain_gemm(actA, 136, wh + OFF_WPOST, 256, nb * 128, 128, bp, c,
                   tid, lane, wm, wn);
        chain_epi_smem(c, actY, 264, nb * 128, b_post + nb * 128, wm, wn, lane);
    }
    __syncthreads();

    // G1 = gv @ W1top + b1 (fp32, no relu) -> global
#pragma unroll 1
    for (int nb = 0; nb < 4; nb++) {
        chain_gemm(actY, 264, wh + OFF_W1, 512, nb * 128, 256, bp, c,
                   tid, lane, wm, wn);
#pragma unroll
        for (int mi = 0; mi < 4; mi++) {
            const int rl0 = wm * 64 + mi * 16 + (lane >> 2);
#pragma unroll
            for (int ni = 0; ni < 4; ni++) {
                const int cl = wn * 32 + ni * 8 + (lane & 3) * 2;
                const float bb0 = b1[nb * 128 + cl], bb1 = b1[nb * 128 + cl + 1];
                float v0 = c[mi][ni][0] + bb0, v1 = c[mi][ni][1] + bb1;
                float v2 = c[mi][ni][2] + bb0, v3 = c[mi][ni][3] + bb1;
                *(float2*)&G1[(size_t)(srow + rl0) * 512 + nb * 128 + cl] =
                    make_float2(v0, v1);
                *(float2*)&G1[(size_t)(srow + rl0 + 8) * 512 + nb * 128 + cl] =
                    make_float2(v2, v3);
            }
        }
    }
}

// ---------------------------------------------------------------------------
__global__ void convW(const float* __restrict__ Wpre, const float* __restrict__ Wloc,
                      const float* __restrict__ Wgcn, const float* __restrict__ Wpost,
                      const float* __restrict__ W1, const float* __restrict__ W2,
                      __half* __restrict__ out)
{
    int idx = blockIdx.x * blockDim.x + threadIdx.x;
    if (idx >= WH_TOTAL) return;
    float v;
    if (idx < OFF_WGCN) {
        int k = idx / 384, j = idx % 384;
        v = (j < 128) ? Wpre[k * 128 + j] : Wloc[k * 256 + (j - 128)];
    }
    else if (idx < OFF_WPOST) v = Wgcn[idx - OFF_WGCN];
    else if (idx < OFF_W1)    v = Wpost[idx - OFF_WPOST];
    else if (idx < OFF_W2)    v = W1[idx - OFF_W1];
    else                      v = W2[idx - OFF_W2];
    out[idx] = __float2half_rn(v);
}

__global__ void fillBcat(const float* __restrict__ b_pre,
                         const float* __restrict__ b_loc, float* __restrict__ bcat)
{
    int i = threadIdx.x;
    bcat[i] = (i < 128) ? b_pre[i] : b_loc[i - 128];
}

// q = sum of 4 q_part + b3
__global__ void qreduce(const float4* __restrict__ qp, const float* __restrict__ b3,
                        float4* __restrict__ q, int n4)
{
    int i = blockIdx.x * blockDim.x + threadIdx.x;
    if (i >= n4) return;
    const float4 b = ((const float4*)b3)[i & 1];
    float4 a0 = qp[i], a1 = qp[n4 + i], a2 = qp[2 * n4 + i], a3 = qp[3 * n4 + i];
    float4 r;
    r.x = a0.x + a1.x + a2.x + a3.x + b.x;
    r.y = a0.y + a1.y + a2.y + a3.y + b.y;
    r.z = a0.z + a1.z + a2.z + a3.z + b.z;
    r.w = a0.w + a1.w + a2.w + a3.w + b.w;
    q[i] = r;
}

// ---------------------------------------------------------------------------
extern "C" void kernel_launch(void* const* d_in, const int* in_sizes, int n_in,
                              void* d_out, int out_size)
{
    const float* obs    = (const float*)d_in[0];
    const float* W_pre  = (const float*)d_in[1];
    const float* b_pre  = (const float*)d_in[2];
    const float* W_gcn  = (const float*)d_in[3];
    const float* b_gcn  = (const float*)d_in[4];
    const float* W_post = (const float*)d_in[5];
    const float* b_post = (const float*)d_in[6];
    const float* W_loc  = (const float*)d_in[7];
    const float* b_loc  = (const float*)d_in[8];
    const float* W1     = (const float*)d_in[9];
    const float* b1     = (const float*)d_in[10];
    const float* W2     = (const float*)d_in[11];
    const float* b2     = (const float*)d_in[12];
    const float* W3     = (const float*)d_in[13];
    const float* b3     = (const float*)d_in[14];
    float* q = (float*)d_out;

    const int Bsz = in_sizes[0] / (NAGENT * OBS);   // 2048
    const int M   = Bsz * NAGENT;                   // 32768

    __half *wh, *loc, *xbar, *z1;
    float *bcat, *G1, *qp;
    cudaGetSymbolAddress((void**)&wh,   g_wh);
    cudaGetSymbolAddress((void**)&bcat, g_bcat);
    cudaGetSymbolAddress((void**)&loc,  g_loc);
    cudaGetSymbolAddress((void**)&xbar, g_xbar);
    cudaGetSymbolAddress((void**)&G1,   g_G1);
    cudaGetSymbolAddress((void**)&z1,   g_z1);
    cudaGetSymbolAddress((void**)&qp,   g_qpart);

    cudaFuncSetAttribute(hgemm<1, 1>, cudaFuncAttributeMaxDynamicSharedMemorySize, SMEMB);
    cudaFuncSetAttribute(hgemm<0, 0>, cudaFuncAttributeMaxDynamicSharedMemorySize, SMEMB);
    cudaFuncSetAttribute(hgemm<0, 2>, cudaFuncAttributeMaxDynamicSharedMemorySize, SMEMB);
    cudaFuncSetAttribute(chain, cudaFuncAttributeMaxDynamicSharedMemorySize, CH_SMEM);

    convW<<<(WH_TOTAL + 255) / 256, 256>>>(W_pre, W_loc, W_gcn, W_post, W1, W2, wh);
    fillBcat<<<1, 384>>>(b_pre, b_loc, bcat);

    // 1) loc = relu(obs @ Wloc + b_loc) (compact [M,256]); block 0 computes x
    //    only for xbar (no global write)
    hgemm<1, 1><<<dim3(3, M / BM), 256, SMEMB>>>(obs, wh + OFF_WCAT, loc, nullptr,
                                                 M, 384, OBS, OBS, 256, 128,
                                                 bcat, nullptr, 1, xbar, nullptr);
    // 2) fused chain: xbar -> s0 -> s1 -> gv -> G1
    chain<<<Bsz / 128, 256, CH_SMEM>>>(xbar, wh, b_gcn, b_post, b1, G1);
    // 3) z1 = relu(loc @ W1bot + G1[sample])            [M,512]
    hgemm<0, 0><<<dim3(F1 / BN, M / BM), 256, SMEMB>>>(loc, wh + OFF_W1 + GE * F1,
                                                       z1, nullptr, M, F1, LE, 256,
                                                       F1, 0, nullptr, G1, 1,
                                                       nullptr, nullptr);
    // 4) fused z2+q: q_part[bx] = relu(z1 @ W2 + b2)[:, bx*128:+128] @ W3-slice
    hgemm<0, 2><<<dim3(F2 / BN, M / BM), 256, SMEMB>>>(z1, wh + OFF_W2, nullptr, qp,
                                                       M, F2, F1, F1, F2, 0,
                                                       b2, nullptr, 1, nullptr, W3);
    // 5) q = sum(q_part) + b3
    qreduce<<<(M * NACT / 4 + 255) / 256, 256>>>((const float4*)qp, b3, (float4*)q,
                                                 M * NACT / 4);
}

// round 11
// speedup vs baseline: 1.6097x; 1.1293x over previous
#include <cuda_runtime.h>
#include <cuda_fp16.h>
#include <cstdint>

#define OBS 128
#define NAGENT 16
#define HID 128
#define GE 256
#define LE 256
#define F1 512
#define F2 512
#define NACT 8
#define MAXB 2048
#define MAXM (MAXB * NAGENT)

// fp16 weight pack offsets (halves)
#define OFF_WCAT  0            // [128, 384] = [W_pre | W_loc]
#define OFF_WGCN  49152        // [2,128,128]
#define OFF_WPOST 81920        // [128,256]
#define OFF_W1    114688       // [512,512]
#define OFF_W2    376832       // [512,512]
#define WH_TOTAL  638976

__device__ __align__(16) __half g_wh[WH_TOTAL];
__device__ __align__(16) float  g_bcat[384];
__device__ __align__(16) __half g_loc[MAXM * 256];    // compact loc
__device__ __align__(16) __half g_xbar[MAXB * HID];
__device__ __align__(16) float  g_G1[MAXB * F1];
__device__ __align__(16) __half g_z1[MAXM * F1];
__device__ __align__(16) float  g_qpart[4 * MAXM * NACT];

#define BM 128
#define BN 128
#define BK 64

// hgemm dynamic smem (halves)
#define A_ST   17920
#define A_RS   72
#define B_OFF  9216
#define B_RS   136
#define PB_ST  8704
#define SMEMB  71680

// chain kernel smem (halves)
#define CH_ACTA 0
#define CH_ACTB 17408
#define CH_ACTY 34816          // 128 x 264
#define CH_BP   68608          // 2 x 8704
#define CH_SMEM ((CH_BP + 2 * PB_ST) * 2)    // 172032 bytes

__device__ __forceinline__ void cp16(uint32_t dst, const void* src) {
    asm volatile("cp.async.cg.shared.global [%0], [%1], 16;\n" ::"r"(dst), "l"(src));
}
__device__ __forceinline__ uint32_t smem_u32(const void* p) {
    return (uint32_t)__cvta_generic_to_shared(p);
}

#define LDSM_A(dst, addr) \
    asm volatile("ldmatrix.sync.aligned.m8n8.x4.shared.b16 {%0,%1,%2,%3}, [%4];" \
                 : "=r"((dst)[0]), "=r"((dst)[1]), "=r"((dst)[2]), "=r"((dst)[3]) \
                 : "r"(addr))
#define LDSM_BT(dst, addr) \
    asm volatile("ldmatrix.sync.aligned.m8n8.x4.trans.shared.b16 {%0,%1,%2,%3}, [%4];" \
                 : "=r"((dst)[0]), "=r"((dst)[1]), "=r"((dst)[2]), "=r"((dst)[3]) \
                 : "r"(addr))
#define MMA16816(cc, a, b0v, b1v) \
    asm volatile("mma.sync.aligned.m16n8k16.row.col.f32.f16.f16.f32 " \
                 "{%0,%1,%2,%3}, {%4,%5,%6,%7}, {%8,%9}, {%0,%1,%2,%3};" \
                 : "+f"((cc)[0]), "+f"((cc)[1]), "+f"((cc)[2]), "+f"((cc)[3]) \
                 : "r"((a)[0]), "r"((a)[1]), "r"((a)[2]), "r"((a)[3]), \
                   "r"(b0v), "r"(b1v))

// ---------------------------------------------------------------------------
// fp16 HMMA GEMM. AF32: A fp32 converted inline. FUSE:
//  0 = plain (writes cols >= ocol, shifted by ocol into C of stride ldc);
//  1 = no writes when col < ocol; block x==0 emits xbar;
//  2 = no C write; q_part[bx] = relu-tile @ W3[bcol:+128,:8] (aux_f=W3).
// bcol0: column offset added to blockIdx.x*BN.
// ---------------------------------------------------------------------------
template <int AF32, int FUSE>
__global__ __launch_bounds__(256) void hgemm(
    const void* __restrict__ Ap, const __half* __restrict__ B,
    __half* __restrict__ Ch, float* __restrict__ Cf,
    int M, int N, int K, int lda, int ldc, int ocol, int bcol0,
    const float* __restrict__ bias, const float* __restrict__ rowAdd,
    int doRelu, __half* __restrict__ aux_h, const float* __restrict__ aux_f)
{
    extern __shared__ __half S[];

    const int tid  = threadIdx.x;
    const int lane = tid & 31;
    const int wid  = tid >> 5;
    const int wm   = wid >> 2;
    const int wn   = wid & 3;
    const int brow = blockIdx.y * BM;
    const int bcol = blockIdx.x * BN + bcol0;

    const __half* Ah = (const __half*)Ap;
    const float*  Af = (const float*)Ap;

    float c[4][4][4];
#pragma unroll
    for (int i = 0; i < 4; i++)
#pragma unroll
        for (int j = 0; j < 4; j++)
#pragma unroll
            for (int e = 0; e < 4; e++) c[i][j][e] = 0.f;

    const int nT = K / BK;

    auto loadStage = [&](int t, int st) {
        const int k0 = t * BK;
        __half* As = S + st * A_ST;
        __half* Bs = S + st * A_ST + B_OFF;
#pragma unroll
        for (int j = 0; j < 4; j++) {
            const int ch = j * 256 + tid;
            const int r = ch >> 3, cc = (ch & 7) * 8;
            if (AF32) {
                const float4* s =
                    (const float4*)(Af + (size_t)(brow + r) * lda + k0 + cc);
                float4 v0 = s[0], v1 = s[1];
                __half2 h0 = __floats2half2_rn(v0.x, v0.y);
                __half2 h1 = __floats2half2_rn(v0.z, v0.w);
                __half2 h2 = __floats2half2_rn(v1.x, v1.y);
                __half2 h3 = __floats2half2_rn(v1.z, v1.w);
                uint4 u;
                u.x = *(uint32_t*)&h0; u.y = *(uint32_t*)&h1;
                u.z = *(uint32_t*)&h2; u.w = *(uint32_t*)&h3;
                *(uint4*)&As[r * A_RS + cc] = u;
            } else {
                cp16(smem_u32(&As[r * A_RS + cc]),
                     Ah + (size_t)(brow + r) * lda + k0 + cc);
            }
        }
#pragma unroll
        for (int j = 0; j < 4; j++) {
            const int ch = j * 256 + tid;
            const int r = ch >> 4, cc = (ch & 15) * 8;
            cp16(smem_u32(&Bs[r * B_RS + cc]),
                 B + (size_t)(k0 + r) * N + bcol + cc);
        }
    };

    loadStage(0, 0);
    asm volatile("cp.async.commit_group;\n");

    for (int t = 0; t < nT; t++) {
        if (t + 1 < nT) loadStage(t + 1, (t + 1) & 1);
        asm volatile("cp.async.commit_group;\n");
        asm volatile("cp.async.wait_group 1;\n");
        __syncthreads();

        const __half* As = S + (t & 1) * A_ST;
        const __half* Bs = S + (t & 1) * A_ST + B_OFF;
#pragma unroll
        for (int ks = 0; ks < 4; ks++) {
            uint32_t a[4][4], b[2][4];
#pragma unroll
            for (int mi = 0; mi < 4; mi++)
                LDSM_A(a[mi], smem_u32(&As[(wm * 64 + mi * 16 + (lane & 15)) * A_RS +
                                           ks * 16 + (lane >> 4) * 8]));
#pragma unroll
            for (int pi = 0; pi < 2; pi++)
                LDSM_BT(b[pi], smem_u32(&Bs[(ks * 16 + (lane & 7) +
                                             ((lane >> 3) & 1) * 8) * B_RS +
                                            wn * 32 + pi * 16 + (lane >> 4) * 8]));
#pragma unroll
            for (int mi = 0; mi < 4; mi++)
#pragma unroll
                for (int ni = 0; ni < 4; ni++)
                    MMA16816(c[mi][ni], a[mi],
                             b[ni >> 1][(ni & 1) * 2], b[ni >> 1][(ni & 1) * 2 + 1]);
        }
        __syncthreads();
    }

    const bool stage = (FUSE == 2) || (FUSE == 1 && blockIdx.x == 0);
    __half* zs = S;

#pragma unroll
    for (int mi = 0; mi < 4; mi++) {
        const int rl0 = wm * 64 + mi * 16 + (lane >> 2);
        const int row  = brow + rl0;
        const int row2 = row + 8;
        const float* ra = rowAdd ? rowAdd + (size_t)(row >> 4) * N : nullptr;
#pragma unroll
        for (int ni = 0; ni < 4; ni++) {
            const int cl  = wn * 32 + ni * 8 + (lane & 3) * 2;
            const int col = bcol + cl;
            float v0 = c[mi][ni][0], v1 = c[mi][ni][1];
            float v2 = c[mi][ni][2], v3 = c[mi][ni][3];
            if (bias) {
                const float bb0 = bias[col], bb1 = bias[col + 1];
                v0 += bb0; v1 += bb1; v2 += bb0; v3 += bb1;
            }
            if (ra) {
                const float r0 = ra[col], r1 = ra[col + 1];
                v0 += r0; v1 += r1; v2 += r0; v3 += r1;
            }
            if (doRelu) {
                v0 = fmaxf(v0, 0.f); v1 = fmaxf(v1, 0.f);
                v2 = fmaxf(v2, 0.f); v3 = fmaxf(v3, 0.f);
            }
            __half2 h01 = __floats2half2_rn(v0, v1);
            __half2 h23 = __floats2half2_rn(v2, v3);
            if (FUSE != 2 && col >= ocol) {
                if (Ch) {
                    *(__half2*)&Ch[(size_t)row  * ldc + col - ocol] = h01;
                    *(__half2*)&Ch[(size_t)row2 * ldc + col - ocol] = h23;
                } else {
                    *(float2*)&Cf[(size_t)row  * ldc + col - ocol] = make_float2(v0, v1);
                    *(float2*)&Cf[(size_t)row2 * ldc + col - ocol] = make_float2(v2, v3);
                }
            }
            if (stage) {
                *(__half2*)&zs[rl0 * B_RS + cl]       = h01;
                *(__half2*)&zs[(rl0 + 8) * B_RS + cl] = h23;
            }
        }
    }

    if (FUSE == 1 && blockIdx.x == 0) {
        __syncthreads();
        const int s0 = brow >> 4;
#pragma unroll
        for (int j = 0; j < 4; j++) {
            const int idx = j * 256 + tid;
            const int s = idx >> 7, cc = idx & 127;
            float acc = 0.f;
#pragma unroll
            for (int r = 0; r < 16; r++)
                acc += __half2float(zs[(s * 16 + r) * B_RS + cc]);
            aux_h[(size_t)(s0 + s) * 128 + cc] = __float2half_rn(acc * (1.f / 16.f));
        }
    }

    if (FUSE == 2) {
        __syncthreads();
        float* W3s = (float*)(zs + 128 * B_RS);
        {
            const float4* src = (const float4*)(aux_f + (size_t)bcol * NACT);
            ((float4*)W3s)[tid] = src[tid];
        }
        __syncthreads();
        const __half2* zs2 = (const __half2*)zs;
        float* qp = Cf + (size_t)blockIdx.x * M * NACT;
        for (int rr = 0; rr < 16; rr++) {
            const int rl = wid * 16 + rr;
            float acc[NACT] = {};
#pragma unroll
            for (int it = 0; it < 2; it++) {
                const int k2 = it * 32 + lane;
                float2 z = __half22float2(zs2[rl * (B_RS / 2) + k2]);
                const float* w0 = &W3s[(2 * k2) * NACT];
#pragma unroll
                for (int n = 0; n < NACT; n++)
                    acc[n] = fmaf(z.x, w0[n], fmaf(z.y, w0[NACT + n], acc[n]));
            }
#pragma unroll
            for (int n = 0; n < NACT; n++)
#pragma unroll
                for (int off = 16; off > 0; off >>= 1)
                    acc[n] += __shfl_xor_sync(0xffffffff, acc[n], off);
            if (lane == 0) {
                float* o = qp + (size_t)(brow + rl) * NACT;
#pragma unroll
                for (int n = 0; n < NACT; n++) o[n] = acc[n];
            }
        }
    }
}

// ---------------------------------------------------------------------------
__device__ __forceinline__ void chain_gemm(
    const __half* __restrict__ act, int actS,
    const __half* __restrict__ Wg, int ldw, int wcol, int K,
    __half* __restrict__ bp, float c[4][4][4],
    int tid, int lane, int wm, int wn)
{
#pragma unroll
    for (int i = 0; i < 4; i++)
#pragma unroll
        for (int j = 0; j < 4; j++)
#pragma unroll
            for (int e = 0; e < 4; e++) c[i][j][e] = 0.f;

    const int nT = K >> 6;
    auto loadB = [&](int t, int st) {
        const int k0 = t * 64;
        __half* Bs = bp + st * PB_ST;
#pragma unroll
        for (int j = 0; j < 4; j++) {
            const int ch = j * 256 + tid;
            const int r = ch >> 4, cc = (ch & 15) * 8;
            cp16(smem_u32(&Bs[r * B_RS + cc]),
                 Wg + (size_t)(k0 + r) * ldw + wcol + cc);
        }
    };

    loadB(0, 0);
    asm volatile("cp.async.commit_group;\n");
    for (int t = 0; t < nT; t++) {
        if (t + 1 < nT) loadB(t + 1, (t + 1) & 1);
        asm volatile("cp.async.commit_group;\n");
        asm volatile("cp.async.wait_group 1;\n");
        __syncthreads();
        const __half* Bs = bp + (t & 1) * PB_ST;
#pragma unroll
        for (int ks = 0; ks < 4; ks++) {
            uint32_t a[4][4], b[2][4];
#pragma unroll
            for (int mi = 0; mi < 4; mi++)
                LDSM_A(a[mi], smem_u32(&act[(wm * 64 + mi * 16 + (lane & 15)) * actS +
                                            t * 64 + ks * 16 + (lane >> 4) * 8]));
#pragma unroll
            for (int pi = 0; pi < 2; pi++)
                LDSM_BT(b[pi], smem_u32(&Bs[(ks * 16 + (lane & 7) +
                                             ((lane >> 3) & 1) * 8) * B_RS +
                                            wn * 32 + pi * 16 + (lane >> 4) * 8]));
#pragma unroll
            for (int mi = 0; mi < 4; mi++)
#pragma unroll
                for (int ni = 0; ni < 4; ni++)
                    MMA16816(c[mi][ni], a[mi],
                             b[ni >> 1][(ni & 1) * 2], b[ni >> 1][(ni & 1) * 2 + 1]);
        }
        __syncthreads();
    }
}

// NOTE: bias indexed by cl (which already includes wn*32) — pass PLAIN base.
__device__ __forceinline__ void chain_epi_smem(
    float c[4][4][4], __half* out, int outS, int ocol,
    const float* __restrict__ bias, int wm, int wn, int lane)
{
#pragma unroll
    for (int mi = 0; mi < 4; mi++) {
        const int rl0 = wm * 64 + mi * 16 + (lane >> 2);
#pragma unroll
        for (int ni = 0; ni < 4; ni++) {
            const int cl = wn * 32 + ni * 8 + (lane & 3) * 2;
            const float bb0 = bias[cl], bb1 = bias[cl + 1];
            float v0 = fmaxf(c[mi][ni][0] + bb0, 0.f);
            float v1 = fmaxf(c[mi][ni][1] + bb1, 0.f);
            float v2 = fmaxf(c[mi][ni][2] + bb0, 0.f);
            float v3 = fmaxf(c[mi][ni][3] + bb1, 0.f);
            *(__half2*)&out[rl0 * outS + ocol + cl]       = __floats2half2_rn(v0, v1);
            *(__half2*)&out[(rl0 + 8) * outS + ocol + cl] = __floats2half2_rn(v2, v3);
        }
    }
}

// ---------------------------------------------------------------------------
// Fused per-sample chain, 4-way split: grid = 4 * Bsz/128.
// CTA (blk>>2) covers rows; all 4 parts redundantly compute s0/s1/gv, then
// part p computes G1 columns [p*128, p*128+128).
// ---------------------------------------------------------------------------
__global__ __launch_bounds__(256) void chain(
    const __half* __restrict__ xbar, const __half* __restrict__ wh,
    const float* __restrict__ b_gcn, const float* __restrict__ b_post,
    const float* __restrict__ b1, float* __restrict__ G1)
{
    extern __shared__ __half S[];
    __half* actA = S + CH_ACTA;
    __half* actB = S + CH_ACTB;
    __half* actY = S + CH_ACTY;
    __half* bp   = S + CH_BP;

    const int tid = threadIdx.x, lane = tid & 31, wid = tid >> 5;
    const int wm = wid >> 2, wn = wid & 3;
    const int srow = (blockIdx.x >> 2) * 128;
    const int part = blockIdx.x & 3;

    // load xbar tile [128,128] -> actA (stride 136)
#pragma unroll
    for (int j = 0; j < 8; j++) {
        const int ch = j * 256 + tid;
        const int r = ch >> 4, cc = (ch & 15) * 8;
        cp16(smem_u32(&actA[r * 136 + cc]), xbar + (size_t)(srow + r) * 128 + cc);
    }
    asm volatile("cp.async.commit_group;\ncp.async.wait_group 0;\n");
    __syncthreads();

    float c[4][4][4];

    // s0 = relu(xbar @ Wgcn0 + b_gcn0) -> actB
    chain_gemm(actA, 136, wh + OFF_WGCN, 128, 0, 128, bp, c, tid, lane, wm, wn);
    chain_epi_smem(c, actB, 136, 0, b_gcn, wm, wn, lane);
    __syncthreads();

    // s1 = relu(s0 @ Wgcn1 + b_gcn1) -> actA
    chain_gemm(actB, 136, wh + OFF_WGCN + 16384, 128, 0, 128, bp, c, tid, lane, wm, wn);
    chain_epi_smem(c, actA, 136, 0, b_gcn + 128, wm, wn, lane);
    __syncthreads();

    // gv = relu(s1 @ Wpost + b_post) -> actY [128,256]
#pragma unroll 1
    for (int nb = 0; nb < 2; nb++) {
        chain_gemm(actA, 136, wh + OFF_WPOST, 256, nb * 128, 128, bp, c,
                   tid, lane, wm, wn);
        chain_epi_smem(c, actY, 264, nb * 128, b_post + nb * 128, wm, wn, lane);
    }
    __syncthreads();

    // G1 block `part` = gv @ W1top[:, part*128:+128] + b1 (fp32, no relu)
    chain_gemm(actY, 264, wh + OFF_W1, 512, part * 128, 256, bp, c,
               tid, lane, wm, wn);
#pragma unroll
    for (int mi = 0; mi < 4; mi++) {
        const int rl0 = wm * 64 + mi * 16 + (lane >> 2);
#pragma unroll
        for (int ni = 0; ni < 4; ni++) {
            const int cl = wn * 32 + ni * 8 + (lane & 3) * 2;
            const float bb0 = b1[part * 128 + cl], bb1 = b1[part * 128 + cl + 1];
            float v0 = c[mi][ni][0] + bb0, v1 = c[mi][ni][1] + bb1;
            float v2 = c[mi][ni][2] + bb0, v3 = c[mi][ni][3] + bb1;
            *(float2*)&G1[(size_t)(srow + rl0) * 512 + part * 128 + cl] =
                make_float2(v0, v1);
            *(float2*)&G1[(size_t)(srow + rl0 + 8) * 512 + part * 128 + cl] =
                make_float2(v2, v3);
        }
    }
}

// ---------------------------------------------------------------------------
__global__ void convW(const float* __restrict__ Wpre, const float* __restrict__ Wloc,
                      const float* __restrict__ Wgcn, const float* __restrict__ Wpost,
                      const float* __restrict__ W1, const float* __restrict__ W2,
                      const float* __restrict__ b_pre, const float* __restrict__ b_loc,
                      __half* __restrict__ out, float* __restrict__ bcat)
{
    int idx = blockIdx.x * blockDim.x + threadIdx.x;
    if (idx >= WH_TOTAL) return;
    if (idx < 384)
        bcat[idx] = (idx < 128) ? b_pre[idx] : b_loc[idx - 128];
    float v;
    if (idx < OFF_WGCN) {
        int k = idx / 384, j = idx % 384;
        v = (j < 128) ? Wpre[k * 128 + j] : Wloc[k * 256 + (j - 128)];
    }
    else if (idx < OFF_WPOST) v = Wgcn[idx - OFF_WGCN];
    else if (idx < OFF_W1)    v = Wpost[idx - OFF_WPOST];
    else if (idx < OFF_W2)    v = W1[idx - OFF_W1];
    else                      v = W2[idx - OFF_W2];
    out[idx] = __float2half_rn(v);
}

// q = sum of 4 q_part + b3
__global__ void qreduce(const float4* __restrict__ qp, const float* __restrict__ b3,
                        float4* __restrict__ q, int n4)
{
    int i = blockIdx.x * blockDim.x + threadIdx.x;
    if (i >= n4) return;
    const float4 b = ((const float4*)b3)[i & 1];
    float4 a0 = qp[i], a1 = qp[n4 + i], a2 = qp[2 * n4 + i], a3 = qp[3 * n4 + i];
    float4 r;
    r.x = a0.x + a1.x + a2.x + a3.x + b.x;
    r.y = a0.y + a1.y + a2.y + a3.y + b.y;
    r.z = a0.z + a1.z + a2.z + a3.z + b.z;
    r.w = a0.w + a1.w + a2.w + a3.w + b.w;
    q[i] = r;
}

// ---------------------------------------------------------------------------
extern "C" void kernel_launch(void* const* d_in, const int* in_sizes, int n_in,
                              void* d_out, int out_size)
{
    const float* obs    = (const float*)d_in[0];
    const float* b_pre  = (const float*)d_in[2];
    const float* W_gcn  = (const float*)d_in[3];
    const float* b_gcn  = (const float*)d_in[4];
    const float* W_post = (const float*)d_in[5];
    const float* b_post = (const float*)d_in[6];
    const float* W_loc  = (const float*)d_in[7];
    const float* b_loc  = (const float*)d_in[8];
    const float* W_pre  = (const float*)d_in[1];
    const float* W1     = (const float*)d_in[9];
    const float* b1     = (const float*)d_in[10];
    const float* W2     = (const float*)d_in[11];
    const float* b2     = (const float*)d_in[12];
    const float* W3     = (const float*)d_in[13];
    const float* b3     = (const float*)d_in[14];
    float* q = (float*)d_out;

    const int Bsz = in_sizes[0] / (NAGENT * OBS);   // 2048
    const int M   = Bsz * NAGENT;                   // 32768

    __half *wh, *loc, *xbar, *z1;
    float *bcat, *G1, *qp;
    cudaGetSymbolAddress((void**)&wh,   g_wh);
    cudaGetSymbolAddress((void**)&bcat, g_bcat);
    cudaGetSymbolAddress((void**)&loc,  g_loc);
    cudaGetSymbolAddress((void**)&xbar, g_xbar);
    cudaGetSymbolAddress((void**)&G1,   g_G1);
    cudaGetSymbolAddress((void**)&z1,   g_z1);
    cudaGetSymbolAddress((void**)&qp,   g_qpart);

    cudaFuncSetAttribute(hgemm<1, 1>, cudaFuncAttributeMaxDynamicSharedMemorySize, SMEMB);
    cudaFuncSetAttribute(hgemm<1, 0>, cudaFuncAttributeMaxDynamicSharedMemorySize, SMEMB);
    cudaFuncSetAttribute(hgemm<0, 0>, cudaFuncAttributeMaxDynamicSharedMemorySize, SMEMB);
    cudaFuncSetAttribute(hgemm<0, 2>, cudaFuncAttributeMaxDynamicSharedMemorySize, SMEMB);
    cudaFuncSetAttribute(chain, cudaFuncAttributeMaxDynamicSharedMemorySize, CH_SMEM);

    // side stream + events for capture-legal fork/join (created per call;
    // never destroyed -- tiny, and only 2 host calls per run)
    cudaStream_t s1;
    cudaStreamCreateWithFlags(&s1, cudaStreamNonBlocking);
    cudaEvent_t eA, eB;
    cudaEventCreateWithFlags(&eA, cudaEventDisableTiming);
    cudaEventCreateWithFlags(&eB, cudaEventDisableTiming);

    // 0) weight conversion (+ bcat)
    convW<<<(WH_TOTAL + 255) / 256, 256>>>(W_pre, W_loc, W_gcn, W_post, W1, W2,
                                           b_pre, b_loc, wh, bcat);

    // 1a) x block only -> xbar (no global writes: ocol=384 > all cols)
    hgemm<1, 1><<<dim3(1, M / BM), 256, SMEMB>>>(obs, wh + OFF_WCAT, loc, nullptr,
                                                 M, 384, OBS, OBS, 256, 384, 0,
                                                 bcat, nullptr, 1, xbar, nullptr);
    cudaEventRecord(eA, 0);

    // chain on side stream, concurrent with 1b
    cudaStreamWaitEvent(s1, eA, 0);
    chain<<<4 * (Bsz / 128), 256, CH_SMEM, s1>>>(xbar, wh, b_gcn, b_post, b1, G1);
    cudaEventRecord(eB, s1);

    // 1b) loc = relu(obs @ Wloc + b_loc) (cols 128..383 -> compact [M,256])
    hgemm<1, 0><<<dim3(2, M / BM), 256, SMEMB>>>(obs, wh + OFF_WCAT, loc, nullptr,
                                                 M, 384, OBS, OBS, 256, 128, 128,
                                                 bcat, nullptr, 1, nullptr, nullptr);

    // join: z1 needs loc (stream 0) and G1 (s1)
    cudaStreamWaitEvent(0, eB, 0);

    // 2) z1 = relu(loc @ W1bot + G1[sample])            [M,512]
    hgemm<0, 0><<<dim3(F1 / BN, M / BM), 256, SMEMB>>>(loc, wh + OFF_W1 + GE * F1,
                                                       z1, nullptr, M, F1, LE, 256,
                                                       F1, 0, 0, nullptr, G1, 1,
                                                       nullptr, nullptr);
    // 3) fused z2+q: q_part[bx] = relu(z1 @ W2 + b2)[:, bx*128:+128] @ W3-slice
    hgemm<0, 2><<<dim3(F2 / BN, M / BM), 256, SMEMB>>>(z1, wh + OFF_W2, nullptr, qp,
                                                       M, F2, F1, F1, F2, 0, 0,
                                                       b2, nullptr, 1, nullptr, W3);
    // 4) q = sum(q_part) + b3
    qreduce<<<(M * NACT / 4 + 255) / 256, 256>>>((const float4*)qp, b3, (float4*)q,
                                                 M * NACT / 4);
}